// round 11
// baseline (speedup 1.0000x reference)
#include <cuda_runtime.h>

// YOLO v1 loss: pred/target (16384, 7, 7, 30) fp32 -> scalar fp32.
// HBM-bound streaming reduction; 192.6 MB input traffic.
// Staging reduces class loss on the fly -> smem ~11.8KB/block -> high occupancy.

#define NBATCH   16384
#define SGRID    7
#define NCELLS   (NBATCH * SGRID * SGRID)   // 802816
#define CPB      128                        // cells per block
#define NBLOCKS  (NCELLS / CPB)             // 6272, exact
#define NF4      (CPB * 30 / 4)             // 960 float4 per array per block
#define L_COORD  5.0f
#define L_NOOBJ  0.5f

__global__ void yolo_zero_out(float* out) {
    if (threadIdx.x == 0) out[0] = 0.0f;
}

__global__ __launch_bounds__(CPB, 10)
void yolo_v1_loss_kernel(const float* __restrict__ pred,
                         const float* __restrict__ targ,
                         float* __restrict__ out) {
    // stride-11 rows (10 used) -> conflict-free per-thread reads in compute phase
    __shared__ float sp10[CPB * 11];
    __shared__ float st10[CPB * 11];
    __shared__ float scls[CPB];
    __shared__ float warp_sums[CPB / 32];

    const int tid = threadIdx.x;
    const long long cell0 = (long long)blockIdx.x * CPB;

    scls[tid] = 0.0f;
    __syncthreads();

    // base offset = blockIdx * 128 * 30 * 4B = multiple of 15360 -> 16B aligned
    const float4* __restrict__ gp = (const float4*)(pred + cell0 * 30);
    const float4* __restrict__ gt = (const float4*)(targ + cell0 * 30);

    #pragma unroll 4
    for (int i = tid; i < NF4; i += CPB) {
        const float4 pv = gp[i];
        const float4 tv = gt[i];
        const float pa[4] = {pv.x, pv.y, pv.z, pv.w};
        const float ta[4] = {tv.x, tv.y, tv.z, tv.w};
        const int e0 = 4 * i;

        // A float4 spans 4 consecutive elements; the class region of at most
        // ONE cell can appear in it (k=29 -> next cell's k=0 is a box elem).
        float acc = 0.0f;
        int   ccell = 0;
        bool  has = false;
        #pragma unroll
        for (int c = 0; c < 4; c++) {
            const int e = e0 + c;
            const int cell = e / 30;
            const int k = e - cell * 30;
            if (k < 10) {
                sp10[cell * 11 + k] = pa[c];
                st10[cell * 11 + k] = ta[c];
            } else {
                const float d = pa[c] - ta[c];
                acc += d * d;
                ccell = cell;
                has = true;
            }
        }
        if (has) atomicAdd(&scls[ccell], acc);
    }
    __syncthreads();

    const float* p = sp10 + tid * 11;
    const float* t = st10 + tid * 11;

    const float coo = (t[4] > 0.0f) ? 1.0f : 0.0f;

    // no-object confidence loss (both boxes' confidences)
    const float d4 = p[4] - t[4];
    const float d9 = p[9] - t[9];
    const float noo_l = d4 * d4 + d9 * d9;

    // class loss already reduced during staging (unweighted sum of squares)
    const float cls = scls[tid];

    // target box 0 corners / area (replicate reference arithmetic exactly)
    const float t0x = t[0], t0y = t[1], t0w = t[2], t0h = t[3];
    const float tltx = t0x - 0.5f * t0w, tlty = t0y - 0.5f * t0h;
    const float trbx = t0x + 0.5f * t0w, trby = t0y + 0.5f * t0h;
    const float area2 = (trbx - tltx) * (trby - tlty);

    float iou[2];
    #pragma unroll
    for (int b = 0; b < 2; b++) {
        const float px = p[b * 5 + 0], py = p[b * 5 + 1];
        const float pw = p[b * 5 + 2], ph = p[b * 5 + 3];
        const float pltx = px - 0.5f * pw, plty = py - 0.5f * ph;
        const float prbx = px + 0.5f * pw, prby = py + 0.5f * ph;
        const float ltx = fmaxf(pltx, tltx), lty = fmaxf(plty, tlty);
        const float rbx = fminf(prbx, trbx), rby = fminf(prby, trby);
        // NOTE: reference indicator is (rb - lt < 0) -> 1.0
        const float ix = ((rbx - ltx) < 0.0f) ? 1.0f : 0.0f;
        const float iy = ((rby - lty) < 0.0f) ? 1.0f : 0.0f;
        const float inter = ix * iy;
        const float area1 = (prbx - pltx) * (prby - plty);
        iou[b] = inter / (area1 + area2 - inter);
    }

    // argmax: first max wins -> idx=1 only when iou1 strictly greater
    const int idx = (iou[1] > iou[0]) ? 1 : 0;
    const float* rp = p + idx * 5;
    const float* rt = t + idx * 5;

    const float dc = rp[4] - rt[4];
    const float contain = dc * dc;

    const float dx = rp[0] - rt[0];
    const float dy = rp[1] - rt[1];

    const bool safe = coo > 0.0f;
    const float swp = sqrtf(safe ? rp[2] : 1.0f);
    const float shp = sqrtf(safe ? rp[3] : 1.0f);
    const float swt = sqrtf(safe ? rt[2] : 1.0f);
    const float sht = sqrtf(safe ? rt[3] : 1.0f);
    const float dw = swp - swt;
    const float dh = shp - sht;

    const float loc = dx * dx + dy * dy + dw * dw + dh * dh;

    float v = coo * (L_COORD * loc + contain + cls)
            + L_NOOBJ * (1.0f - coo) * noo_l;
    v *= (1.0f / (float)NBATCH);

    // block reduction
    #pragma unroll
    for (int off = 16; off > 0; off >>= 1)
        v += __shfl_down_sync(0xffffffffu, v, off);
    if ((tid & 31) == 0) warp_sums[tid >> 5] = v;
    __syncthreads();
    if (tid == 0) {
        float s = 0.0f;
        #pragma unroll
        for (int w = 0; w < CPB / 32; w++) s += warp_sums[w];
        atomicAdd(out, s);
    }
}

extern "C" void kernel_launch(void* const* d_in, const int* in_sizes, int n_in,
                              void* d_out, int out_size) {
    const float* pred = (const float*)d_in[0];
    const float* targ = (const float*)d_in[1];
    float* out = (float*)d_out;

    yolo_zero_out<<<1, 32>>>(out);
    yolo_v1_loss_kernel<<<NBLOCKS, CPB>>>(pred, targ, out);
}

// round 12
// speedup vs baseline: 1.2078x; 1.2078x over previous
#include <cuda_runtime.h>

// YOLO v1 loss: pred/target (16384, 7, 7, 30) fp32 -> scalar fp32.
// HBM-bound streaming reduction; 192.6 MB input traffic.
// cp.async double-buffered persistent pipeline: loads always in flight.

#define NBATCH   16384
#define SGRID    7
#define NCELLS   (NBATCH * SGRID * SGRID)   // 802816
#define CPB      128                        // cells per tile (= threads per block)
#define NTILES   (NCELLS / CPB)             // 6272, exact
#define NF4      (CPB * 30 / 4)             // 960 float4 per array per tile
#define GRID     444                        // 148 SMs * 3 blocks -> one wave
#define L_COORD  5.0f
#define L_NOOBJ  0.5f

// dynamic smem layout: [bufP0 | bufT0 | bufP1 | bufT1], each NF4 float4
#define SMEM_BYTES (4 * NF4 * 16)

__global__ void yolo_zero_out(float* out) {
    if (threadIdx.x == 0) out[0] = 0.0f;
}

__device__ __forceinline__ void cp16(float4* s, const float4* g) {
    unsigned saddr = (unsigned)__cvta_generic_to_shared(s);
    asm volatile("cp.async.cg.shared.global [%0], [%1], 16;\n"
                 :: "r"(saddr), "l"(g));
}

__device__ __forceinline__ void prefetch_tile(const float* __restrict__ pred,
                                              const float* __restrict__ targ,
                                              int tile, float4* sP, float4* sT,
                                              int tid) {
    const float4* gp = (const float4*)(pred + (long long)tile * (CPB * 30));
    const float4* gt = (const float4*)(targ + (long long)tile * (CPB * 30));
    #pragma unroll
    for (int j = 0; j < 7; j++) {
        cp16(sP + tid + CPB * j, gp + tid + CPB * j);
        cp16(sT + tid + CPB * j, gt + tid + CPB * j);
    }
    if (tid < (NF4 - 7 * CPB)) {          // 960 - 896 = 64 tail float4s
        cp16(sP + tid + 7 * CPB, gp + tid + 7 * CPB);
        cp16(sT + tid + 7 * CPB, gt + tid + 7 * CPB);
    }
}

__device__ __forceinline__ float cell_loss(const float* __restrict__ p,
                                           const float* __restrict__ t) {
    const float coo = (t[4] > 0.0f) ? 1.0f : 0.0f;

    // no-object confidence loss (both boxes' confidences)
    const float d4 = p[4] - t[4];
    const float d9 = p[9] - t[9];
    const float noo_l = d4 * d4 + d9 * d9;

    // class loss (elements 10..29)
    float cls = 0.0f;
    #pragma unroll
    for (int k = 10; k < 30; k++) {
        const float d = p[k] - t[k];
        cls += d * d;
    }

    // target box 0 corners / area (replicate reference arithmetic exactly)
    const float t0x = t[0], t0y = t[1], t0w = t[2], t0h = t[3];
    const float tltx = t0x - 0.5f * t0w, tlty = t0y - 0.5f * t0h;
    const float trbx = t0x + 0.5f * t0w, trby = t0y + 0.5f * t0h;
    const float area2 = (trbx - tltx) * (trby - tlty);

    float iou[2];
    #pragma unroll
    for (int b = 0; b < 2; b++) {
        const float px = p[b * 5 + 0], py = p[b * 5 + 1];
        const float pw = p[b * 5 + 2], ph = p[b * 5 + 3];
        const float pltx = px - 0.5f * pw, plty = py - 0.5f * ph;
        const float prbx = px + 0.5f * pw, prby = py + 0.5f * ph;
        const float ltx = fmaxf(pltx, tltx), lty = fmaxf(plty, tlty);
        const float rbx = fminf(prbx, trbx), rby = fminf(prby, trby);
        // NOTE: reference indicator is (rb - lt < 0) -> 1.0
        const float ix = ((rbx - ltx) < 0.0f) ? 1.0f : 0.0f;
        const float iy = ((rby - lty) < 0.0f) ? 1.0f : 0.0f;
        const float inter = ix * iy;
        const float area1 = (prbx - pltx) * (prby - plty);
        iou[b] = inter / (area1 + area2 - inter);
    }

    // argmax: first max wins -> idx=1 only when iou1 strictly greater
    const int idx = (iou[1] > iou[0]) ? 1 : 0;
    const float* rp = p + idx * 5;
    const float* rt = t + idx * 5;

    const float dc = rp[4] - rt[4];
    const float contain = dc * dc;

    const float dx = rp[0] - rt[0];
    const float dy = rp[1] - rt[1];

    const bool safe = coo > 0.0f;
    const float swp = sqrtf(safe ? rp[2] : 1.0f);
    const float shp = sqrtf(safe ? rp[3] : 1.0f);
    const float swt = sqrtf(safe ? rt[2] : 1.0f);
    const float sht = sqrtf(safe ? rt[3] : 1.0f);
    const float dw = swp - swt;
    const float dh = shp - sht;

    const float loc = dx * dx + dy * dy + dw * dw + dh * dh;

    return coo * (L_COORD * loc + contain + cls)
         + L_NOOBJ * (1.0f - coo) * noo_l;
}

extern __shared__ float4 smem4[];

__global__ __launch_bounds__(CPB, 3)
void yolo_v1_loss_kernel(const float* __restrict__ pred,
                         const float* __restrict__ targ,
                         float* __restrict__ out) {
    __shared__ float warp_sums[CPB / 32];

    const int tid = threadIdx.x;
    float4* bufP[2] = { smem4,           smem4 + 2 * NF4 };
    float4* bufT[2] = { smem4 + NF4,     smem4 + 3 * NF4 };

    // first tile for this block
    int t = blockIdx.x;
    prefetch_tile(pred, targ, t, bufP[0], bufT[0], tid);
    asm volatile("cp.async.commit_group;\n" ::: "memory");

    float vsum = 0.0f;
    int cur = 0;

    for (; t < NTILES; t += GRID) {
        // issue next tile's loads into the other buffer BEFORE computing
        const int tn = t + GRID;
        if (tn < NTILES)
            prefetch_tile(pred, targ, tn, bufP[cur ^ 1], bufT[cur ^ 1], tid);
        asm volatile("cp.async.commit_group;\n" ::: "memory");
        // complete all but the most recent group -> current tile resident
        asm volatile("cp.async.wait_group 1;\n" ::: "memory");
        __syncthreads();

        const float* p = (const float*)bufP[cur] + tid * 30;
        const float* tt = (const float*)bufT[cur] + tid * 30;
        vsum += cell_loss(p, tt);

        __syncthreads();   // everyone done reading before this buffer is refilled
        cur ^= 1;
    }

    vsum *= (1.0f / (float)NBATCH);

    // block reduction
    #pragma unroll
    for (int off = 16; off > 0; off >>= 1)
        vsum += __shfl_down_sync(0xffffffffu, vsum, off);
    if ((tid & 31) == 0) warp_sums[tid >> 5] = vsum;
    __syncthreads();
    if (tid == 0) {
        float s = 0.0f;
        #pragma unroll
        for (int w = 0; w < CPB / 32; w++) s += warp_sums[w];
        atomicAdd(out, s);
    }
}

extern "C" void kernel_launch(void* const* d_in, const int* in_sizes, int n_in,
                              void* d_out, int out_size) {
    const float* pred = (const float*)d_in[0];
    const float* targ = (const float*)d_in[1];
    float* out = (float*)d_out;

    cudaFuncSetAttribute(yolo_v1_loss_kernel,
                         cudaFuncAttributeMaxDynamicSharedMemorySize, SMEM_BYTES);

    yolo_zero_out<<<1, 32>>>(out);
    yolo_v1_loss_kernel<<<GRID, CPB, SMEM_BYTES>>>(pred, targ, out);
}